// round 15
// baseline (speedup 1.0000x reference)
#include <cuda_runtime.h>
#include <cstdint>

// Shapes (fixed):
//   x [16,512,64,64] f32 | w [16,512] | weight [512,512,3,3] | affine_w [512,512]
//   affine_b [512] | out [16,512,64,64] f32
#define NB   16
#define NC   512
#define NH   64
#define NW   64
#define NHW  4096

// -------- device scratch --------
__device__ float  g_s [NB * NC];          // modulation scale s[b,i]
__device__ float  g_w2[NC * NC];          // W2[o,i] = sum_k weight^2
__device__ float  g_d [NB * NC];          // demod d[b,o]
// A operand, fragment-permuted, tf32-rounded (proven in R11):
//   tile = (pos*4 + cb)*16 + cc ; within tile: ((ks*2+wm)*4+im)*32 + lane
//   float4 = { W[m][k], W[m+8][k], W[m][k+4], W[m+8][k+4] }
//   m = cb*128 + wm*64 + im*16 + (lane>>2), k = cc*32 + ks*8 + (lane&3)
__device__ float4 g_wt4[9 * NC * NC / 4];

// -------- helpers --------
__device__ __forceinline__ uint32_t f2tf32(float f) {
    uint32_t r; asm("cvt.rna.tf32.f32 %0, %1;" : "=r"(r) : "f"(f)); return r;
}

__device__ __forceinline__ void mma_tf32(float* c, const uint32_t* a, const uint32_t* b) {
    asm volatile(
        "mma.sync.aligned.m16n8k8.row.col.f32.tf32.tf32.f32 "
        "{%0,%1,%2,%3}, {%4,%5,%6,%7}, {%8,%9}, {%0,%1,%2,%3};"
        : "+f"(c[0]), "+f"(c[1]), "+f"(c[2]), "+f"(c[3])
        : "r"(a[0]), "r"(a[1]), "r"(a[2]), "r"(a[3]),
          "r"(b[0]), "r"(b[1]));
}

// -------- prep kernels --------
__global__ void k_modscale(const float* __restrict__ w,
                           const float* __restrict__ aw,
                           const float* __restrict__ ab) {
    int b = blockIdx.y, warp = threadIdx.x >> 5, lane = threadIdx.x & 31;
    int i = blockIdx.x * 8 + warp;
    const float* wrow = w + b * NC;
    const float* arow = aw + i * NC;
    float sum = 0.f;
#pragma unroll
    for (int j = lane; j < NC; j += 32) sum += wrow[j] * arow[j];
#pragma unroll
    for (int off = 16; off; off >>= 1) sum += __shfl_xor_sync(0xffffffffu, sum, off);
    if (lane == 0) g_s[b * NC + i] = sum + ab[i] + 1.0f;
}

__global__ void k_w2(const float* __restrict__ weight) {
    int idx = blockIdx.x * blockDim.x + threadIdx.x;   // < 262144
    const float* p = weight + (size_t)idx * 9;
    float s = 0.f;
#pragma unroll
    for (int t = 0; t < 9; t++) s += p[t] * p[t];
    g_w2[idx] = s;
}

// fragment-permute weights into g_wt4 (one float4 per thread, coalesced stores)
__global__ void k_wtperm(const float* __restrict__ weight) {
    int fidx = blockIdx.x * blockDim.x + threadIdx.x;   // < 589824
    int widx = fidx & 1023;
    int tile = fidx >> 10;                              // 0..575
    int cc   = tile & 15;
    int tmp  = tile >> 4;
    int cb   = tmp & 3;
    int pos  = tmp >> 2;                                // 0..8
    int lane = widx & 31;
    int im   = (widx >> 5) & 3;
    int wm   = (widx >> 7) & 1;
    int ks   = widx >> 8;
    int g = lane >> 2, t = lane & 3;
    int co = cb * 128 + wm * 64 + im * 16 + g;
    int ci = cc * 32 + ks * 8 + t;
    float4 v;
    v.x = __uint_as_float(f2tf32(weight[((co    ) * NC + ci    ) * 9 + pos]));
    v.y = __uint_as_float(f2tf32(weight[((co + 8) * NC + ci    ) * 9 + pos]));
    v.z = __uint_as_float(f2tf32(weight[((co    ) * NC + ci + 4) * 9 + pos]));
    v.w = __uint_as_float(f2tf32(weight[((co + 8) * NC + ci + 4) * 9 + pos]));
    g_wt4[fidx] = v;
}

__global__ void k_demod() {
    int b = blockIdx.y, warp = threadIdx.x >> 5, lane = threadIdx.x & 31;
    int o = blockIdx.x * 8 + warp;
    const float* srow = g_s + b * NC;
    const float* w2r  = g_w2 + o * NC;
    float sum = 0.f;
#pragma unroll
    for (int j = lane; j < NC; j += 32) { float sv = srow[j]; sum += sv * sv * w2r[j]; }
#pragma unroll
    for (int off = 16; off; off >>= 1) sum += __shfl_xor_sync(0xffffffffu, sum, off);
    if (lane == 0) g_d[b * NC + o] = rsqrtf(sum + 1e-8f);
}

// -------- main conv: tf32 mma.sync, 64x64 warp tiles, pre-scaled halo, LDS.128 A --
// CTA 128 thr (4 warps, 2x2). Tile M=128 co x N=128 px (2 rows) x K=32 ci/iter.
// A: 2-slot cp.async double buffer of permuted 16KB tiles (frag = 1 LDS.128).
// B: double-buffered halo; raw x staged via 4B cp.async (zero-fill OOB) at
//    pos 1..7, then scaled+tf32-rounded IN PLACE (12 elems/thread/iter) at
//    pos 3..8 (each group >= 2 iters after its commit -> visible). mma B loads
//    are plain scalar LDS of ready tf32 values.

#define ASZ    4096                  // floats per permuted A slot (16 KB)
#define BKS    292                   // halo k-stride (292 % 32 == 4): conflict-free
#define BRS    68                    // halo row stride (4 rows x 66 used cols)
#define HSZ    (32 * BKS)            // 9344 floats per halo buffer
#define SMEM_FLOATS (2 * ASZ + 2 * HSZ + NC)
#define SMEM_BYTES  (SMEM_FLOATS * 4)   // 109568 B -> 2 CTAs/SM

__device__ __forceinline__ void prefA(const float4* __restrict__ src, float* dstbuf,
                                      int tid) {
#pragma unroll
    for (int j = 0; j < 8; j++) {
        int ch = tid + 128 * j;            // 0..1023
        uint32_t dst = (uint32_t)__cvta_generic_to_shared(dstbuf + ch * 4);
        asm volatile("cp.async.cg.shared.global [%0], [%1], 16;"
                     :: "r"(dst), "l"(src + ch));
    }
    asm volatile("cp.async.commit_group;" ::: "memory");
}

// stage one halo element via 4B cp.async; OOB -> zero-fill (src-size 0)
__device__ __forceinline__ void stage1(const float* __restrict__ xk, float* hbuf,
                                       int j, int tid, int row0) {
    int idx = tid + 128 * j;               // < 8704 = 32*272
    int k   = idx / 272;
    int rem = idx - k * 272;
    int r   = rem / BRS;
    int c   = rem - r * BRS;
    int xr  = row0 - 1 + r, xc = c - 1;
    bool ok = ((unsigned)xr < (unsigned)NH) && ((unsigned)xc < (unsigned)NW);
    int off = ok ? ((xr << 6) + xc) : 0;
    const float* src = xk + (k << 12) + off;
    uint32_t dst = (uint32_t)__cvta_generic_to_shared(hbuf + k * BKS + r * BRS + c);
    uint32_t sz  = ok ? 4u : 0u;
    asm volatile("cp.async.ca.shared.global [%0], [%1], 4, %2;"
                 :: "r"(dst), "l"(src), "r"(sz));
}

// scale one staged halo element in place: h = tf32(h * s[ci])
__device__ __forceinline__ void scale1(float* hbuf, const float* sA,
                                       int j, int tid) {
    int idx = tid + 128 * j;
    int k   = idx / 272;
    int rem = idx - k * 272;
    float* p = hbuf + k * BKS + rem;       // rem = r*BRS + c directly
    *p = __uint_as_float(f2tf32(*p * sA[k]));
}

__global__ void __launch_bounds__(128, 2)
k_conv(const float* __restrict__ x, float* __restrict__ out) {
    extern __shared__ float smem[];
    float* As   = smem;                    // 2 x 4096 (permuted A)
    float* halo = smem + 2 * ASZ;          // 2 x 9344
    float* sS   = smem + 2 * ASZ + 2 * HSZ;

    const int tid  = threadIdx.x;
    const int wid  = tid >> 5;
    const int lane = tid & 31;
    const int wm   = wid >> 1;             // 0..1 (64 M-rows each)
    const int wn   = wid & 1;              // 0..1 (64 N-cols each)
    const int g    = lane >> 2;            // 0..7
    const int t    = lane & 3;             // 0..3

    const int b       = blockIdx.z;
    const int row0    = blockIdx.y * 2;
    const int cb      = blockIdx.x;        // co block (x128)
    const int co_base = cb * 128;

#pragma unroll
    for (int j = 0; j < 4; j++) sS[tid + 128 * j] = g_s[b * NC + tid + 128 * j];

    const float* xb = x + (size_t)b * NC * NHW;

    // stage halo chunk 0 (raw x) + commit; prefetch A(it=0)
#pragma unroll
    for (int j = 0; j < 68; j++) stage1(xb, halo, j, tid, row0);
    asm volatile("cp.async.commit_group;" ::: "memory");
    prefA(g_wt4 + (size_t)(cb * 16) * 1024, As, tid);

    asm volatile("cp.async.wait_group 0;" ::: "memory");
    __syncthreads();                       // chunk-0 halo + sS visible
    // scale chunk 0 in place
#pragma unroll
    for (int j = 0; j < 68; j++) scale1(halo, sS, j, tid);

    // per-thread B fragment n-offsets (n = wn*64 + in*8 + g)
    int noff[8];
#pragma unroll
    for (int in = 0; in < 8; in++) {
        int n = wn * 64 + in * 8 + g;
        noff[in] = (n >> 6) * BRS + (n & 63);
    }

    float acc[4][8][4];
#pragma unroll
    for (int im = 0; im < 4; im++)
#pragma unroll
        for (int in = 0; in < 8; in++)
#pragma unroll
            for (int q = 0; q < 4; q++) acc[im][in][q] = 0.f;

    int pos = 0, cc = 0;
#pragma unroll 1
    for (int it = 0; it < 144; ++it) {
        // ---- stage 10 raw elems of NEXT chunk's halo (pos 1..7) ----
        if (pos >= 1 && cc < 15) {
            float* hn = halo + ((cc + 1) & 1) * HSZ;
            const float* xk = xb + (size_t)((cc + 1) * 32) * NHW;
#pragma unroll
            for (int jj = 0; jj < 10; jj++) {
                int j = (pos - 1) * 10 + jj;
                if (j < 68) stage1(xk, hn, j, tid, row0);
            }
        }

        asm volatile("cp.async.wait_group 0;" ::: "memory");   // A(it)+older staging
        __syncthreads();   // single barrier: A(it)+halo visible; mma(it-1) done

        // ---- prefetch A(it+1); commits pending staging ops with it ----
        if (it + 1 < 144) {
            int np = pos + 1, ncc = cc;
            if (np == 9) { np = 0; ncc++; }
            prefA(g_wt4 + ((size_t)(np * 4 + cb) * 16 + ncc) * 1024,
                  As + ((it + 1) & 1) * ASZ, tid);
        }

        // ---- scale 12 elems of NEXT chunk's halo in place (pos 3..8) ----
        if (pos >= 3 && cc < 15) {
            float* hn = halo + ((cc + 1) & 1) * HSZ;
            const float* sA = sS + (cc + 1) * 32;
#pragma unroll
            for (int jj = 0; jj < 12; jj++) {
                int j = (pos - 3) * 12 + jj;
                if (j < 68) scale1(hn, sA, j, tid);
            }
        }

        // ---- mma block: 4 k-steps x 32 mma; operands ready in smem ----
        {
            const int kh = pos / 3 - 1;
            const int kw = pos - (pos / 3) * 3 - 1;
            const float4* Ab = (const float4*)(As + (it & 1) * ASZ);
            const float* Bb = halo + (cc & 1) * HSZ + (1 + kh) * BRS + (1 + kw);
#pragma unroll
            for (int ks = 0; ks < 4; ++ks) {
                const int krow = ks * 8 + t;
                float4 afv[4];
                const float4* ap = Ab + ((ks * 2 + wm) * 4) * 32 + lane;
#pragma unroll
                for (int im = 0; im < 4; im++) afv[im] = ap[im * 32];
                uint32_t bf[8][2];
#pragma unroll
                for (int in = 0; in < 8; in++) {
                    const float* p = Bb + krow * BKS + noff[in];
                    bf[in][0] = __float_as_uint(p[0]);
                    bf[in][1] = __float_as_uint(p[4 * BKS]);
                }
#pragma unroll
                for (int im = 0; im < 4; im++) {
                    uint32_t af[4] = { __float_as_uint(afv[im].x), __float_as_uint(afv[im].y),
                                       __float_as_uint(afv[im].z), __float_as_uint(afv[im].w) };
#pragma unroll
                    for (int in = 0; in < 8; in++)
                        mma_tf32(acc[im][in], af, bf[in]);
                }
            }
        }

        if (++pos == 9) { pos = 0; cc++; }
    }

    // ---- epilogue: scale by d[b,co], store float2 ----
    float* ob = out + (size_t)(b * NC + co_base) * NHW + row0 * NW;
#pragma unroll
    for (int im = 0; im < 4; im++) {
        int m0 = wm * 64 + im * 16 + g;
        float d0 = g_d[b * NC + co_base + m0];
        float d1 = g_d[b * NC + co_base + m0 + 8];
#pragma unroll
        for (int in = 0; in < 8; in++) {
            int n = wn * 64 + in * 8 + t * 2;
            float2 v0 = make_float2(acc[im][in][0] * d0, acc[im][in][1] * d0);
            float2 v1 = make_float2(acc[im][in][2] * d1, acc[im][in][3] * d1);
            *(float2*)(ob + (size_t)m0 * NHW + n)       = v0;
            *(float2*)(ob + (size_t)(m0 + 8) * NHW + n) = v1;
        }
    }
}

// -------- launch --------
extern "C" void kernel_launch(void* const* d_in, const int* in_sizes, int n_in,
                              void* d_out, int out_size) {
    (void)in_sizes; (void)n_in; (void)out_size;
    const float* x      = (const float*)d_in[0];
    const float* w      = (const float*)d_in[1];
    const float* weight = (const float*)d_in[2];
    const float* aw     = (const float*)d_in[3];
    const float* ab     = (const float*)d_in[4];
    float* out = (float*)d_out;

    static bool attr_set = false;
    if (!attr_set) {
        cudaFuncSetAttribute(k_conv, cudaFuncAttributeMaxDynamicSharedMemorySize,
                             SMEM_BYTES);
        attr_set = true;
    }

    k_modscale<<<dim3(64, 16), 256>>>(w, aw, ab);
    k_w2<<<1024, 256>>>(weight);
    k_wtperm<<<2304, 256>>>(weight);      // 589824 / 256
    k_demod<<<dim3(64, 16), 256>>>();
    k_conv<<<dim3(4, 32, 16), 128, SMEM_BYTES>>>(x, out);
}

// round 17
// speedup vs baseline: 1.2674x; 1.2674x over previous
#include <cuda_runtime.h>
#include <cstdint>

// Shapes (fixed):
//   x [16,512,64,64] f32 | w [16,512] | weight [512,512,3,3] | affine_w [512,512]
//   affine_b [512] | out [16,512,64,64] f32
#define NB   16
#define NC   512
#define NH   64
#define NW   64
#define NHW  4096

// -------- device scratch --------
__device__ float  g_s [NB * NC];          // modulation scale s[b,i]
__device__ float  g_w2[NC * NC];          // W2[o,i] = sum_k weight^2
__device__ float  g_d [NB * NC];          // demod d[b,o]
__device__ float4 g_xs[NB * NC * NHW / 4];// xs = tf32(x * s[b,ci])  (128 MB scratch)
// A operand, fragment-permuted, tf32-rounded (proven R11/R15):
//   tile = (pos*4 + cb)*16 + cc ; within tile: ((ks*2+wm)*4+im)*32 + lane
//   float4 = { W[m][k], W[m+8][k], W[m][k+4], W[m+8][k+4] }
//   m = cb*128 + wm*64 + im*16 + (lane>>2), k = cc*32 + ks*8 + (lane&3)
__device__ float4 g_wt4[9 * NC * NC / 4];

// -------- helpers --------
__device__ __forceinline__ uint32_t f2tf32(float f) {
    uint32_t r; asm("cvt.rna.tf32.f32 %0, %1;" : "=r"(r) : "f"(f)); return r;
}

__device__ __forceinline__ void mma_tf32(float* c, const uint32_t* a, const uint32_t* b) {
    asm volatile(
        "mma.sync.aligned.m16n8k8.row.col.f32.tf32.tf32.f32 "
        "{%0,%1,%2,%3}, {%4,%5,%6,%7}, {%8,%9}, {%0,%1,%2,%3};"
        : "+f"(c[0]), "+f"(c[1]), "+f"(c[2]), "+f"(c[3])
        : "r"(a[0]), "r"(a[1]), "r"(a[2]), "r"(a[3]),
          "r"(b[0]), "r"(b[1]));
}

// -------- prep kernels --------
__global__ void k_modscale(const float* __restrict__ w,
                           const float* __restrict__ aw,
                           const float* __restrict__ ab) {
    int b = blockIdx.y, warp = threadIdx.x >> 5, lane = threadIdx.x & 31;
    int i = blockIdx.x * 8 + warp;
    const float* wrow = w + b * NC;
    const float* arow = aw + i * NC;
    float sum = 0.f;
#pragma unroll
    for (int j = lane; j < NC; j += 32) sum += wrow[j] * arow[j];
#pragma unroll
    for (int off = 16; off; off >>= 1) sum += __shfl_xor_sync(0xffffffffu, sum, off);
    if (lane == 0) g_s[b * NC + i] = sum + ab[i] + 1.0f;
}

__global__ void k_w2(const float* __restrict__ weight) {
    int idx = blockIdx.x * blockDim.x + threadIdx.x;   // < 262144
    const float* p = weight + (size_t)idx * 9;
    float s = 0.f;
#pragma unroll
    for (int t = 0; t < 9; t++) s += p[t] * p[t];
    g_w2[idx] = s;
}

// fragment-permute weights into g_wt4 (one float4 per thread, coalesced stores)
__global__ void k_wtperm(const float* __restrict__ weight) {
    int fidx = blockIdx.x * blockDim.x + threadIdx.x;   // < 589824
    int widx = fidx & 1023;
    int tile = fidx >> 10;                              // 0..575
    int cc   = tile & 15;
    int tmp  = tile >> 4;
    int cb   = tmp & 3;
    int pos  = tmp >> 2;                                // 0..8
    int lane = widx & 31;
    int im   = (widx >> 5) & 3;
    int wm   = (widx >> 7) & 1;
    int ks   = widx >> 8;
    int g = lane >> 2, t = lane & 3;
    int co = cb * 128 + wm * 64 + im * 16 + g;
    int ci = cc * 32 + ks * 8 + t;
    float4 v;
    v.x = __uint_as_float(f2tf32(weight[((co    ) * NC + ci    ) * 9 + pos]));
    v.y = __uint_as_float(f2tf32(weight[((co + 8) * NC + ci    ) * 9 + pos]));
    v.z = __uint_as_float(f2tf32(weight[((co    ) * NC + ci + 4) * 9 + pos]));
    v.w = __uint_as_float(f2tf32(weight[((co + 8) * NC + ci + 4) * 9 + pos]));
    g_wt4[fidx] = v;
}

__global__ void k_demod() {
    int b = blockIdx.y, warp = threadIdx.x >> 5, lane = threadIdx.x & 31;
    int o = blockIdx.x * 8 + warp;
    const float* srow = g_s + b * NC;
    const float* w2r  = g_w2 + o * NC;
    float sum = 0.f;
#pragma unroll
    for (int j = lane; j < NC; j += 32) { float sv = srow[j]; sum += sv * sv * w2r[j]; }
#pragma unroll
    for (int off = 16; off; off >>= 1) sum += __shfl_xor_sync(0xffffffffu, sum, off);
    if (lane == 0) g_d[b * NC + o] = rsqrtf(sum + 1e-8f);
}

// pre-scaled activations: g_xs = tf32(x * s[b,ci]), float4-vectorized
// total float4 elements: 16*512*4096/4 = 8388608
__global__ void k_xs(const float* __restrict__ x) {
    int i = blockIdx.x * blockDim.x + threadIdx.x;   // < 8388608 float4
    float4 xv = ((const float4*)x)[i];
    int ci = (i >> 10) & 511;                        // 1024 float4 per (b,ci) plane
    int b  = i >> 19;
    float s = g_s[b * NC + ci];
    float4 o;
    o.x = __uint_as_float(f2tf32(xv.x * s));
    o.y = __uint_as_float(f2tf32(xv.y * s));
    o.z = __uint_as_float(f2tf32(xv.z * s));
    o.w = __uint_as_float(f2tf32(xv.w * s));
    g_xs[i] = o;
}

// -------- main conv: tf32 mma.sync, 64x64 warp tiles, zero in-loop ALU ---------
// CTA 128 thr (4 warps, 2x2). Tile M=128 co x N=128 px (2 rows) x K=32 ci/iter.
// A: 2-slot cp.async double buffer of permuted tiles (frag = 1 LDS.128).
// B: double-buffered halo of PRE-SCALED tf32 x (from g_xs), stored k-PAIRED:
//    float2 {x[k], x[k+4]} so each mma B fragment is one LDS.64. Staged via
//    4B cp.async (zero-fill OOB), 10 elems/thread/iter during pos 1..7.

#define ASZ   4096                   // floats per permuted A slot (16 KB)
#define PS2   276                    // float2 pitch per (ks,t) row; 276%16==4 -> CF
#define BRS2  69                     // pixel row pitch inside a (ks,t) row (float2)
#define HSZ2  (16 * PS2)             // 4416 float2 per halo buffer
#define SMEM_FLOATS (2 * ASZ + 2 * HSZ2 * 2)
#define SMEM_BYTES  (SMEM_FLOATS * 4)   // 103424 B -> 2 CTAs/SM

__device__ __forceinline__ void prefA(const float4* __restrict__ src, float* dstbuf,
                                      int tid) {
#pragma unroll
    for (int j = 0; j < 8; j++) {
        int ch = tid + 128 * j;            // 0..1023
        uint32_t dst = (uint32_t)__cvta_generic_to_shared(dstbuf + ch * 4);
        asm volatile("cp.async.cg.shared.global [%0], [%1], 16;"
                     :: "r"(dst), "l"(src + ch));
    }
    asm volatile("cp.async.commit_group;" ::: "memory");
}

// stage one pre-scaled halo element via 4B cp.async into the k-paired layout;
// OOB -> zero-fill (src-size 0)
__device__ __forceinline__ void stage1(const float* __restrict__ xk, float* hbuf,
                                       int j, int tid, int row0) {
    int idx = tid + 128 * j;               // < 8704 = 32*272
    int k   = idx / 272;                   // ci row 0..31
    int rem = idx - k * 272;
    int r   = rem / 68;                    // halo row 0..3
    int c   = rem - r * 68;                // halo col 0..67
    int xr  = row0 - 1 + r, xc = c - 1;
    bool ok = ((unsigned)xr < (unsigned)NH) && ((unsigned)xc < (unsigned)NW);
    int off = ok ? ((xr << 6) + xc) : 0;
    const float* src = xk + (k << 12) + off;
    int trow = k & 3, comp = (k >> 2) & 1, ks = k >> 3;
    int dstf = ((((ks * 4 + trow) * PS2) + r * BRS2 + c) << 1) + comp;
    uint32_t dst = (uint32_t)__cvta_generic_to_shared(hbuf + dstf);
    uint32_t sz  = ok ? 4u : 0u;
    asm volatile("cp.async.ca.shared.global [%0], [%1], 4, %2;"
                 :: "r"(dst), "l"(src), "r"(sz));
}

__global__ void __launch_bounds__(128, 2)
k_conv(float* __restrict__ out) {
    extern __shared__ float smem[];
    float* As   = smem;                    // 2 x 4096 (permuted A)
    float* halo = smem + 2 * ASZ;          // 2 x 8832 floats (k-paired tf32 x*s)

    const int tid  = threadIdx.x;
    const int wid  = tid >> 5;
    const int lane = tid & 31;
    const int wm   = wid >> 1;             // 0..1 (64 M-rows each)
    const int wn   = wid & 1;              // 0..1 (64 N-cols each)
    const int g    = lane >> 2;            // 0..7
    const int t    = lane & 3;             // 0..3

    const int b       = blockIdx.z;
    const int row0    = blockIdx.y * 2;
    const int cb      = blockIdx.x;        // co block (x128)
    const int co_base = cb * 128;

    const float* xb = (const float*)g_xs + (size_t)b * NC * NHW;

    // stage halo chunk 0 + commit; prefetch A(it=0)
#pragma unroll
    for (int j = 0; j < 68; j++) stage1(xb, halo, j, tid, row0);
    asm volatile("cp.async.commit_group;" ::: "memory");
    prefA(g_wt4 + (size_t)(cb * 16) * 1024, As, tid);

    // per-thread B fragment pixel offsets (float2 units): n = wn*64 + in*8 + g
    int noff[8];
#pragma unroll
    for (int in = 0; in < 8; in++) {
        int n = wn * 64 + in * 8 + g;
        noff[in] = (n >> 6) * BRS2 + (n & 63);
    }

    float acc[4][8][4];
#pragma unroll
    for (int im = 0; im < 4; im++)
#pragma unroll
        for (int in = 0; in < 8; in++)
#pragma unroll
            for (int q = 0; q < 4; q++) acc[im][in][q] = 0.f;

    int pos = 0, cc = 0;
#pragma unroll 1
    for (int it = 0; it < 144; ++it) {
        // ---- stage 10 elems of NEXT chunk's halo (cp.async, no stall) ----
        if (pos >= 1 && cc < 15) {
            float* hn = halo + ((cc + 1) & 1) * (2 * HSZ2);
            const float* xk = xb + (size_t)((cc + 1) * 32) * NHW;
#pragma unroll
            for (int jj = 0; jj < 10; jj++) {
                int j = (pos - 1) * 10 + jj;
                if (j < 68) stage1(xk, hn, j, tid, row0);
            }
        }

        asm volatile("cp.async.wait_group 0;" ::: "memory");   // A(it)+older staging
        __syncthreads();   // single barrier: A(it)+halo visible; mma(it-1) done

        // ---- prefetch A(it+1); commits pending staging ops with it ----
        if (it + 1 < 144) {
            int np = pos + 1, ncc = cc;
            if (np == 9) { np = 0; ncc++; }
            prefA(g_wt4 + ((size_t)(np * 4 + cb) * 16 + ncc) * 1024,
                  As + ((it + 1) & 1) * ASZ, tid);
        }

        // ---- mma block: 4 k-steps x 32 mma; B frag = 1 LDS.64, zero ALU ----
        {
            const int kh = pos / 3 - 1;
            const int kw = pos - (pos / 3) * 3 - 1;
            const float4* Ab = (const float4*)(As + (it & 1) * ASZ);
            const float2* Bb2 = (const float2*)(halo + (cc & 1) * (2 * HSZ2))
                              + (1 + kh) * BRS2 + (1 + kw);
#pragma unroll
            for (int ks = 0; ks < 4; ++ks) {
                float4 afv[4];
                const float4* ap = Ab + ((ks * 2 + wm) * 4) * 32 + lane;
#pragma unroll
                for (int im = 0; im < 4; im++) afv[im] = ap[im * 32];
                float2 bfv[8];
                const float2* bp = Bb2 + (ks * 4 + t) * PS2;
#pragma unroll
                for (int in = 0; in < 8; in++) bfv[in] = bp[noff[in]];
#pragma unroll
                for (int im = 0; im < 4; im++) {
                    uint32_t af[4] = { __float_as_uint(afv[im].x), __float_as_uint(afv[im].y),
                                       __float_as_uint(afv[im].z), __float_as_uint(afv[im].w) };
#pragma unroll
                    for (int in = 0; in < 8; in++) {
                        uint32_t bf[2] = { __float_as_uint(bfv[in].x),
                                           __float_as_uint(bfv[in].y) };
                        mma_tf32(acc[im][in], af, bf);
                    }
                }
            }
        }

        if (++pos == 9) { pos = 0; cc++; }
    }

    // ---- epilogue: scale by d[b,co], store float2 ----
    float* ob = out + (size_t)(b * NC + co_base) * NHW + row0 * NW;
#pragma unroll
    for (int im = 0; im < 4; im++) {
        int m0 = wm * 64 + im * 16 + g;
        float d0 = g_d[b * NC + co_base + m0];
        float d1 = g_d[b * NC + co_base + m0 + 8];
#pragma unroll
        for (int in = 0; in < 8; in++) {
            int n = wn * 64 + in * 8 + t * 2;
            float2 v0 = make_float2(acc[im][in][0] * d0, acc[im][in][1] * d0);
            float2 v1 = make_float2(acc[im][in][2] * d1, acc[im][in][3] * d1);
            *(float2*)(ob + (size_t)m0 * NHW + n)       = v0;
            *(float2*)(ob + (size_t)(m0 + 8) * NHW + n) = v1;
        }
    }
}

// -------- launch --------
extern "C" void kernel_launch(void* const* d_in, const int* in_sizes, int n_in,
                              void* d_out, int out_size) {
    (void)in_sizes; (void)n_in; (void)out_size;
    const float* x      = (const float*)d_in[0];
    const float* w      = (const float*)d_in[1];
    const float* weight = (const float*)d_in[2];
    const float* aw     = (const float*)d_in[3];
    const float* ab     = (const float*)d_in[4];
    float* out = (float*)d_out;

    static bool attr_set = false;
    if (!attr_set) {
        cudaFuncSetAttribute(k_conv, cudaFuncAttributeMaxDynamicSharedMemorySize,
                             SMEM_BYTES);
        attr_set = true;
    }

    k_modscale<<<dim3(64, 16), 256>>>(w, aw, ab);
    k_w2<<<1024, 256>>>(weight);
    k_wtperm<<<2304, 256>>>(weight);      // 589824 / 256
    k_demod<<<dim3(64, 16), 256>>>();
    k_xs<<<32768, 256>>>(x);              // 8388608 float4 / 256
    k_conv<<<dim3(4, 32, 16), 128, SMEM_BYTES>>>(out);
}